// round 1
// baseline (speedup 1.0000x reference)
#include <cuda_runtime.h>

// VectorQuantizer: x [N,256] fp32, emb [K,256] fp32.
// Outputs (flattened, fp32): quantized [N*256] | loss [1] | indices [N].
//
// distances = ||x||^2 - 2 x@emb.T + ||emb||^2 ; idx = argmin_k (first min)
// quantized_out = x + (emb[idx] - x)   (fp32 rounding replicated)
// loss = L + 0.25*L where L = mean((emb[idx]-x)^2) in fp32 structure.
//
// Rounding replication is load-bearing: distances sit on a ~1 ULP(256) grid,
// so we compute d = fl(fl(S - 2*M) + c) exactly as the reference formula does,
// with S = sequential fp32 sum of individually-rounded squares.

#define DIM  256
#define NMAX 65536
#define KMAX 4096
#define TM 64
#define TN 64
#define TD 16

__device__ float  g_S[NMAX];
__device__ float  g_c[KMAX];
__device__ int    g_idx[NMAX];
__device__ double g_acc;

// ---------------------------------------------------------------------------
// c[k] = sum_i fl(emb[k][i]^2), sequential fp32. Also zeroes the loss
// accumulator (once per launch/replay).
// ---------------------------------------------------------------------------
__global__ __launch_bounds__(256) void k_c(const float* __restrict__ emb, int K) {
    int k = blockIdx.x * blockDim.x + threadIdx.x;
    if (k == 0) g_acc = 0.0;
    if (k >= K) return;
    const float* e = emb + (size_t)k * DIM;
    float s = 0.0f;
    #pragma unroll 8
    for (int i = 0; i < DIM; i++) {
        s = __fadd_rn(s, __fmul_rn(e[i], e[i]));
    }
    g_c[k] = s;
}

// S[n] = sum_i fl(x[n][i]^2), sequential fp32 (hypothesis: matches ref order)
__global__ __launch_bounds__(256) void k_S(const float* __restrict__ x, int N) {
    int n = blockIdx.x * blockDim.x + threadIdx.x;
    if (n >= N) return;
    const float* row = x + (size_t)n * DIM;
    float s = 0.0f;
    #pragma unroll 8
    for (int i = 0; i < DIM; i++) {
        s = __fadd_rn(s, __fmul_rn(row[i], row[i]));
    }
    g_S[n] = s;
}

// ---------------------------------------------------------------------------
// Tiled fp32 GEMM (64 rows x 64 codes per tile) with fused per-row argmin.
// Ties broken by lowest code index (jnp.argmin semantics).
// ---------------------------------------------------------------------------
__global__ __launch_bounds__(256) void k_argmin(const float* __restrict__ x,
                                                const float* __restrict__ emb,
                                                int N, int K) {
    __shared__ float sx[TD][TM + 4];   // +4 pad keeps float4 rows 16B-aligned
    __shared__ float se[TD][TN + 4];
    __shared__ float sS[TM];
    __shared__ float sc[TN];
    __shared__ float cd[TM][16];
    __shared__ int   ci[TM][16];

    const int tid = threadIdx.x;
    const int tx  = tid & 15;
    const int ty  = tid >> 4;
    const int rb  = blockIdx.x * TM;

    const int lm  = tid >> 2;          // 0..63 : smem tile row loaded
    const int ld4 = (tid & 3) * 4;     // 0,4,8,12 : d-offset within stage

    if (tid < TM) sS[tid] = g_S[rb + tid];

    float bd = 3.402823466e38f;        // running best distance for row rb+tid
    int   bi = 0x7fffffff;

    for (int ct = 0; ct < K; ct += TN) {
        if (tid < TN) sc[tid] = g_c[ct + tid];

        float acc[4][4];
        #pragma unroll
        for (int i = 0; i < 4; i++)
            #pragma unroll
            for (int j = 0; j < 4; j++) acc[i][j] = 0.0f;

        for (int dt = 0; dt < DIM; dt += TD) {
            __syncthreads();
            {
                const float4 v = *reinterpret_cast<const float4*>(
                    x + (size_t)(rb + lm) * DIM + dt + ld4);
                sx[ld4 + 0][lm] = v.x; sx[ld4 + 1][lm] = v.y;
                sx[ld4 + 2][lm] = v.z; sx[ld4 + 3][lm] = v.w;
                const float4 w = *reinterpret_cast<const float4*>(
                    emb + (size_t)(ct + lm) * DIM + dt + ld4);
                se[ld4 + 0][lm] = w.x; se[ld4 + 1][lm] = w.y;
                se[ld4 + 2][lm] = w.z; se[ld4 + 3][lm] = w.w;
            }
            __syncthreads();
            #pragma unroll
            for (int d = 0; d < TD; d++) {
                const float4 a = *reinterpret_cast<const float4*>(&sx[d][ty * 4]);
                const float4 b = *reinterpret_cast<const float4*>(&se[d][tx * 4]);
                acc[0][0] = fmaf(a.x, b.x, acc[0][0]);
                acc[0][1] = fmaf(a.x, b.y, acc[0][1]);
                acc[0][2] = fmaf(a.x, b.z, acc[0][2]);
                acc[0][3] = fmaf(a.x, b.w, acc[0][3]);
                acc[1][0] = fmaf(a.y, b.x, acc[1][0]);
                acc[1][1] = fmaf(a.y, b.y, acc[1][1]);
                acc[1][2] = fmaf(a.y, b.z, acc[1][2]);
                acc[1][3] = fmaf(a.y, b.w, acc[1][3]);
                acc[2][0] = fmaf(a.z, b.x, acc[2][0]);
                acc[2][1] = fmaf(a.z, b.y, acc[2][1]);
                acc[2][2] = fmaf(a.z, b.z, acc[2][2]);
                acc[2][3] = fmaf(a.z, b.w, acc[2][3]);
                acc[3][0] = fmaf(a.w, b.x, acc[3][0]);
                acc[3][1] = fmaf(a.w, b.y, acc[3][1]);
                acc[3][2] = fmaf(a.w, b.z, acc[3][2]);
                acc[3][3] = fmaf(a.w, b.w, acc[3][3]);
            }
        }

        // distances + per-thread argmin over its 4 codes (ascending index)
        #pragma unroll
        for (int i = 0; i < 4; i++) {
            const int   r  = ty * 4 + i;
            const float Sv = sS[r];
            float best = 3.402823466e38f;
            int   besti = 0x7fffffff;
            #pragma unroll
            for (int j = 0; j < 4; j++) {
                // d = fl(fl(S - 2*M) + c) : 2*M exact, FMA gives single rounding
                float t1   = __fmaf_rn(-2.0f, acc[i][j], Sv);
                float dist = __fadd_rn(t1, sc[tx * 4 + j]);
                int   kidx = ct + tx * 4 + j;
                if (dist < best) { best = dist; besti = kidx; }
            }
            cd[r][tx] = best;
            ci[r][tx] = besti;
        }
        __syncthreads();
        if (tid < TM) {
            #pragma unroll
            for (int t = 0; t < 16; t++) {
                float dcand = cd[tid][t];
                int   icand = ci[tid][t];
                if (dcand < bd || (dcand == bd && icand < bi)) {
                    bd = dcand; bi = icand;
                }
            }
        }
        __syncthreads();
    }

    if (tid < TM) g_idx[rb + tid] = bi;
}

// ---------------------------------------------------------------------------
// Epilogue: quantized = fl(x + fl(emb[idx]-x)), loss partials in fp64,
// indices as float.
// ---------------------------------------------------------------------------
__global__ __launch_bounds__(256) void k_epi(const float* __restrict__ x,
                                             const float* __restrict__ emb,
                                             float* __restrict__ out,
                                             float* __restrict__ outIdx,
                                             int N) {
    __shared__ double red[256];
    const int t = blockIdx.x * blockDim.x + threadIdx.x;
    const int nvec = N * (DIM / 4);
    double ls = 0.0;
    if (t < nvec) {
        const int n   = t >> 6;               // / (DIM/4)
        const int idx = g_idx[n];
        const float4 xv = reinterpret_cast<const float4*>(x)[t];
        const float4 ev = reinterpret_cast<const float4*>(emb)
                              [(size_t)idx * (DIM / 4) + (t & 63)];
        float d0 = __fsub_rn(ev.x, xv.x);
        float d1 = __fsub_rn(ev.y, xv.y);
        float d2 = __fsub_rn(ev.z, xv.z);
        float d3 = __fsub_rn(ev.w, xv.w);
        float4 o;
        o.x = __fadd_rn(xv.x, d0);
        o.y = __fadd_rn(xv.y, d1);
        o.z = __fadd_rn(xv.z, d2);
        o.w = __fadd_rn(xv.w, d3);
        reinterpret_cast<float4*>(out)[t] = o;
        ls  = (double)__fmul_rn(d0, d0) + (double)__fmul_rn(d1, d1)
            + (double)__fmul_rn(d2, d2) + (double)__fmul_rn(d3, d3);
        if (outIdx != nullptr && (t & 63) == 0) outIdx[n] = (float)idx;
    }
    red[threadIdx.x] = ls;
    __syncthreads();
    #pragma unroll
    for (int s = 128; s > 0; s >>= 1) {
        if (threadIdx.x < s) red[threadIdx.x] += red[threadIdx.x + s];
        __syncthreads();
    }
    if (threadIdx.x == 0) atomicAdd(&g_acc, red[0]);
}

__global__ void k_fin(float* __restrict__ out, int N) {
    double m = g_acc / ((double)N * (double)DIM);
    float L = (float)m;
    out[(size_t)N * DIM] = __fadd_rn(L, __fmul_rn(0.25f, L));
}

// ---------------------------------------------------------------------------
extern "C" void kernel_launch(void* const* d_in, const int* in_sizes, int n_in,
                              void* d_out, int out_size) {
    const float* x   = (const float*)d_in[0];
    const float* emb = (const float*)d_in[1];
    const int N = in_sizes[0] / DIM;   // 65536
    const int K = in_sizes[1] / DIM;   // 4096
    float* out = (float*)d_out;

    const long long Nq = (long long)N * DIM;
    const bool has_loss = (long long)out_size > Nq;
    const bool has_idx  = (long long)out_size >= Nq + 1 + N;
    float* outIdx = has_idx ? out + Nq + 1 : nullptr;

    k_c<<<(K + 255) / 256, 256>>>(emb, K);
    k_S<<<(N + 255) / 256, 256>>>(x, N);
    k_argmin<<<N / TM, 256>>>(x, emb, N, K);
    k_epi<<<(N * (DIM / 4) + 255) / 256, 256>>>(x, emb, out, outIdx, N);
    if (has_loss) k_fin<<<1, 1>>>(out, N);
}